// round 4
// baseline (speedup 1.0000x reference)
#include <cuda_runtime.h>
#include <math.h>
#include <stddef.h>

#define BB   16
#define SSQ  512
#define DDIM 512
#define VV   32000
#define KBM  4
#define TT   64
#define SOS_T 1
#define EOS_T 2
#define PAD_T 0
#define NEGV (-1e9f)
#define NBLK 250          // logits gemm blocks: 32000/128

// ---------------- device scratch (static, no runtime alloc) ----------------
__device__ float g_encK[BB * SSQ * DDIM];          // 16 MB
__device__ float g_q[BB * KBM * DDIM];
__device__ float g_att[BB * KBM * SSQ];
__device__ float g_eCtx[BB * KBM * DDIM];
__device__ float g_pmax[64 * NBLK];
__device__ float g_psum[64 * NBLK];
__device__ float g_ptv[64 * NBLK * 4];
__device__ int   g_pti[64 * NBLK * 4];
__device__ float g_scores[2][BB * KBM];
__device__ int   g_fin[2][BB * KBM];
__device__ int   g_seqs[2][BB * KBM * TT];

// ---------------- generic tiled fp32 GEMM (used for encK precompute) -------
__device__ __forceinline__ void gemm_body(const float* __restrict__ A,
                                          const float* __restrict__ Bm,
                                          float* __restrict__ C,
                                          int M, int N)
{
    __shared__ float As[16][64];
    __shared__ float Bs[16][128];
    const int Kd = 512;
    int tid = threadIdx.x;
    int n0 = blockIdx.x * 128;
    int m0 = blockIdx.y * 64;
    int ty = tid >> 4;
    int tx = tid & 15;

    float acc[4][8];
#pragma unroll
    for (int i = 0; i < 4; i++)
#pragma unroll
        for (int j = 0; j < 8; j++) acc[i][j] = 0.f;

    int am = tid >> 2, aks = (tid & 3) * 4;
    int br = tid >> 4, bc = (tid & 15) * 8;
    float4 pa = make_float4(0.f, 0.f, 0.f, 0.f);
    if (m0 + am < M) pa = *(const float4*)(A + (size_t)(m0 + am) * Kd + aks);
    float4 pb0 = *(const float4*)(Bm + (size_t)br * N + n0 + bc);
    float4 pb1 = *(const float4*)(Bm + (size_t)br * N + n0 + bc + 4);

    for (int k0 = 0; k0 < Kd; k0 += 16) {
        As[aks + 0][am] = pa.x; As[aks + 1][am] = pa.y;
        As[aks + 2][am] = pa.z; As[aks + 3][am] = pa.w;
        *(float4*)&Bs[br][bc] = pb0;
        *(float4*)&Bs[br][bc + 4] = pb1;
        __syncthreads();
        if (k0 + 16 < Kd) {
            pa = make_float4(0.f, 0.f, 0.f, 0.f);
            if (m0 + am < M) pa = *(const float4*)(A + (size_t)(m0 + am) * Kd + k0 + 16 + aks);
            pb0 = *(const float4*)(Bm + (size_t)(k0 + 16 + br) * N + n0 + bc);
            pb1 = *(const float4*)(Bm + (size_t)(k0 + 16 + br) * N + n0 + bc + 4);
        }
#pragma unroll
        for (int kk = 0; kk < 16; kk++) {
            float a0 = As[kk][ty * 4 + 0];
            float a1 = As[kk][ty * 4 + 1];
            float a2 = As[kk][ty * 4 + 2];
            float a3 = As[kk][ty * 4 + 3];
            float4 b0 = *(const float4*)&Bs[kk][tx * 4];
            float4 b1 = *(const float4*)&Bs[kk][64 + tx * 4];
            float bv[8] = {b0.x, b0.y, b0.z, b0.w, b1.x, b1.y, b1.z, b1.w};
#pragma unroll
            for (int j = 0; j < 8; j++) {
                acc[0][j] += a0 * bv[j];
                acc[1][j] += a1 * bv[j];
                acc[2][j] += a2 * bv[j];
                acc[3][j] += a3 * bv[j];
            }
        }
        __syncthreads();
    }
#pragma unroll
    for (int i = 0; i < 4; i++) {
        int m = m0 + ty * 4 + i;
        if (m < M) {
            *(float4*)(C + (size_t)m * N + n0 + tx * 4) =
                make_float4(acc[i][0], acc[i][1], acc[i][2], acc[i][3]);
            *(float4*)(C + (size_t)m * N + n0 + 64 + tx * 4) =
                make_float4(acc[i][4], acc[i][5], acc[i][6], acc[i][7]);
        }
    }
}

__global__ __launch_bounds__(256) void k_gemm_encK(const float* __restrict__ enc,
                                                   const float* __restrict__ Wk)
{
    gemm_body(enc, Wk, g_encK, BB * SSQ, DDIM);
}

// ---------------- logits GEMM + fused per-row lse/top4 epilogue ------------
// grid 250 blocks, 256 threads; tile 64x128, per-thread 4x8, reg-prefetch.
__global__ __launch_bounds__(256) void k_gemm_logits(const float* __restrict__ Wfc,
                                                     const float* __restrict__ bfc)
{
    __shared__ float As[16][64];
    __shared__ float Bs[16][128];
    const float* A = g_eCtx;
    const int N = VV;
    int tid = threadIdx.x;
    int bx = blockIdx.x;
    int n0 = bx * 128;
    int ty = tid >> 4;
    int tx = tid & 15;

    float acc[4][8];
#pragma unroll
    for (int i = 0; i < 4; i++)
#pragma unroll
        for (int j = 0; j < 8; j++) acc[i][j] = 0.f;

    int am = tid >> 2, aks = (tid & 3) * 4;
    int br = tid >> 4, bc = (tid & 15) * 8;
    float4 pa = *(const float4*)(A + (size_t)am * 512 + aks);
    float4 pb0 = *(const float4*)(Wfc + (size_t)br * N + n0 + bc);
    float4 pb1 = *(const float4*)(Wfc + (size_t)br * N + n0 + bc + 4);

    for (int k0 = 0; k0 < 512; k0 += 16) {
        As[aks + 0][am] = pa.x; As[aks + 1][am] = pa.y;
        As[aks + 2][am] = pa.z; As[aks + 3][am] = pa.w;
        *(float4*)&Bs[br][bc] = pb0;
        *(float4*)&Bs[br][bc + 4] = pb1;
        __syncthreads();
        if (k0 + 16 < 512) {
            pa = *(const float4*)(A + (size_t)am * 512 + k0 + 16 + aks);
            pb0 = *(const float4*)(Wfc + (size_t)(k0 + 16 + br) * N + n0 + bc);
            pb1 = *(const float4*)(Wfc + (size_t)(k0 + 16 + br) * N + n0 + bc + 4);
        }
#pragma unroll
        for (int kk = 0; kk < 16; kk++) {
            float a0 = As[kk][ty * 4 + 0];
            float a1 = As[kk][ty * 4 + 1];
            float a2 = As[kk][ty * 4 + 2];
            float a3 = As[kk][ty * 4 + 3];
            float4 b0 = *(const float4*)&Bs[kk][tx * 4];
            float4 b1 = *(const float4*)&Bs[kk][64 + tx * 4];
            float bv[8] = {b0.x, b0.y, b0.z, b0.w, b1.x, b1.y, b1.z, b1.w};
#pragma unroll
            for (int j = 0; j < 8; j++) {
                acc[0][j] += a0 * bv[j];
                acc[1][j] += a1 * bv[j];
                acc[2][j] += a2 * bv[j];
                acc[3][j] += a3 * bv[j];
            }
        }
        __syncthreads();
    }

    // bias
    float4 bias0 = *(const float4*)(bfc + n0 + tx * 4);
    float4 bias1 = *(const float4*)(bfc + n0 + 64 + tx * 4);

    // fused epilogue: per row (ty*4+i) across the 16-thread half-warp group
    // (threads tid = ty*16 + tx all share lane-group [0..15] or [16..31]).
#pragma unroll
    for (int i = 0; i < 4; i++) {
        int row = ty * 4 + i;
        float vals[8];
        int gcols[8];
        vals[0] = acc[i][0] + bias0.x; gcols[0] = n0 + tx * 4 + 0;
        vals[1] = acc[i][1] + bias0.y; gcols[1] = n0 + tx * 4 + 1;
        vals[2] = acc[i][2] + bias0.z; gcols[2] = n0 + tx * 4 + 2;
        vals[3] = acc[i][3] + bias0.w; gcols[3] = n0 + tx * 4 + 3;
        vals[4] = acc[i][4] + bias1.x; gcols[4] = n0 + 64 + tx * 4 + 0;
        vals[5] = acc[i][5] + bias1.y; gcols[5] = n0 + 64 + tx * 4 + 1;
        vals[6] = acc[i][6] + bias1.z; gcols[6] = n0 + 64 + tx * 4 + 2;
        vals[7] = acc[i][7] + bias1.w; gcols[7] = n0 + 64 + tx * 4 + 3;

        // max over 128 cols
        float mx = vals[0];
#pragma unroll
        for (int j = 1; j < 8; j++) mx = fmaxf(mx, vals[j]);
#pragma unroll
        for (int off = 8; off; off >>= 1)
            mx = fmaxf(mx, __shfl_xor_sync(0xffffffffu, mx, off));
        // sum exp
        float se = 0.f;
#pragma unroll
        for (int j = 0; j < 8; j++) se += expf(vals[j] - mx);
#pragma unroll
        for (int off = 8; off; off >>= 1)
            se += __shfl_xor_sync(0xffffffffu, se, off);
        // top-4 (jax tie: lower index first)
        unsigned usedmask = 0;
#pragma unroll
        for (int round = 0; round < 4; round++) {
            float bvv = -3.4e38f; int bcc = 0x7fffffff;
#pragma unroll
            for (int j = 0; j < 8; j++) {
                if (!((usedmask >> j) & 1u)) {
                    if (vals[j] > bvv || (vals[j] == bvv && gcols[j] < bcc)) {
                        bvv = vals[j]; bcc = gcols[j];
                    }
                }
            }
#pragma unroll
            for (int off = 8; off; off >>= 1) {
                float ov = __shfl_xor_sync(0xffffffffu, bvv, off);
                int oc = __shfl_xor_sync(0xffffffffu, bcc, off);
                if (ov > bvv || (ov == bvv && oc < bcc)) { bvv = ov; bcc = oc; }
            }
#pragma unroll
            for (int j = 0; j < 8; j++)
                if (gcols[j] == bcc) usedmask |= 1u << j;
            if (tx == 0) {
                g_ptv[(size_t)row * (NBLK * 4) + bx * 4 + round] = bvv;
                g_pti[(size_t)row * (NBLK * 4) + bx * 4 + round] = bcc;
            }
        }
        if (tx == 0) {
            g_pmax[row * NBLK + bx] = mx;
            g_psum[row * NBLK + bx] = se;
        }
    }
}

// ---------------- embed + q = e @ W_q --------------------------------------
// grid (8 dchunks, 16 b), 256 threads.
__global__ __launch_bounds__(256) void k_embed_q(const float* __restrict__ emb,
                                                 const float* __restrict__ Wq,
                                                 int init, int t, int par)
{
    __shared__ float se[4][512];
    __shared__ int stk[4];
    int b = blockIdx.y, dc = blockIdx.x, tid = threadIdx.x;
    if (tid < 4) stk[tid] = init ? SOS_T : g_seqs[par][(b * 4 + tid) * TT + (t - 1)];
    __syncthreads();
    for (int i = tid; i < 512; i += 256) {
        int k = i >> 7, dl = i & 127;
        ((float4*)se[k])[dl] = ((const float4*)(emb + (size_t)stk[k] * DDIM))[dl];
    }
    __syncthreads();
    int k = tid >> 6, dl = tid & 63, d = dc * 64 + dl;
    const float* wp = Wq + d;
    float a[8];
#pragma unroll
    for (int u = 0; u < 8; u++) a[u] = 0.f;
#pragma unroll 8
    for (int j = 0; j < 512; j += 8) {
#pragma unroll
        for (int u = 0; u < 8; u++)
            a[u] += se[k][j + u] * wp[(size_t)(j + u) * DDIM];
    }
    g_q[(b * 4 + k) * DDIM + d] =
        ((a[0] + a[1]) + (a[2] + a[3])) + ((a[4] + a[5]) + (a[6] + a[7]));
}

// ---------------- attention scores -----------------------------------------
__global__ __launch_bounds__(512) void k_attn(const int* __restrict__ lens, float scale)
{
    __shared__ float sq[4][512];
    int b = blockIdx.y, sc = blockIdx.x, tid = threadIdx.x;
    ((float4*)sq)[tid] = ((const float4*)(g_q + (size_t)b * 4 * DDIM))[tid];
    __syncthreads();
    int warp = tid >> 5, lane = tid & 31;
    int len = lens[b];
    for (int dot = warp; dot < 512; dot += 16) {
        int k = dot >> 7, sl = dot & 127, s = sc * 128 + sl;
        const float4* ek = (const float4*)(g_encK + ((size_t)b * SSQ + s) * DDIM);
        const float4* qk = (const float4*)sq[k];
        float acc = 0.f;
#pragma unroll
        for (int i = 0; i < 4; i++) {
            int j = lane + i * 32;
            float4 a = ek[j], c = qk[j];
            acc += a.x * c.x + a.y * c.y + a.z * c.z + a.w * c.w;
        }
#pragma unroll
        for (int off = 16; off; off >>= 1) acc += __shfl_down_sync(0xffffffffu, acc, off);
        if (lane == 0)
            g_att[(b * 4 + k) * SSQ + s] = (s < len) ? acc * scale : NEGV;
    }
}

// ---------------- softmax + ctx + (e + ctx) --------------------------------
// grid (8 dchunks, 16 b), 256 threads.
__global__ __launch_bounds__(256) void k_ctx(const float* __restrict__ enc,
                                             const float* __restrict__ emb,
                                             int init, int t, int par)
{
    __shared__ float sp[4][512];
    __shared__ int stk[4];
    int b = blockIdx.y, dc = blockIdx.x, tid = threadIdx.x;
    if (tid < 4) stk[tid] = init ? SOS_T : g_seqs[par][(b * 4 + tid) * TT + (t - 1)];
    ((float4*)sp)[tid] = ((const float4*)(g_att + (size_t)b * 4 * SSQ))[tid];
    ((float4*)sp)[tid + 256] = ((const float4*)(g_att + (size_t)b * 4 * SSQ))[tid + 256];
    __syncthreads();
    int warp = tid >> 5, lane = tid & 31;
    if (warp < 4) {
        int k = warp;
        float m = -3.4e38f;
#pragma unroll
        for (int i = 0; i < 16; i++) m = fmaxf(m, sp[k][lane + i * 32]);
#pragma unroll
        for (int off = 16; off; off >>= 1) m = fmaxf(m, __shfl_xor_sync(0xffffffffu, m, off));
        float sum = 0.f;
        float ev[16];
#pragma unroll
        for (int i = 0; i < 16; i++) {
            float e = expf(sp[k][lane + i * 32] - m);
            ev[i] = e;
            sum += e;
        }
#pragma unroll
        for (int off = 16; off; off >>= 1) sum += __shfl_xor_sync(0xffffffffu, sum, off);
        float inv = 1.f / sum;
#pragma unroll
        for (int i = 0; i < 16; i++) sp[k][lane + i * 32] = ev[i] * inv;
    }
    __syncthreads();
    int k = tid >> 6, dl = tid & 63, d = dc * 64 + dl;
    const float* ep = enc + (size_t)b * SSQ * DDIM + d;
    float a[8];
#pragma unroll
    for (int u = 0; u < 8; u++) a[u] = 0.f;
#pragma unroll 4
    for (int s = 0; s < 512; s += 8) {
#pragma unroll
        for (int u = 0; u < 8; u++)
            a[u] += sp[k][s + u] * ep[(size_t)(s + u) * DDIM];
    }
    g_eCtx[(b * 4 + k) * DDIM + d] =
        emb[(size_t)stk[k] * DDIM + d] +
        (((a[0] + a[1]) + (a[2] + a[3])) + ((a[4] + a[5]) + (a[6] + a[7])));
}

// ---------------- merge partials + beam select/combine ----------------------
// grid 16 (b), 256 threads. t==0 -> init select; else combine step t.
__global__ __launch_bounds__(256) void k_merge(int t, int par)
{
    int b = blockIdx.x, tid = threadIdx.x;
    __shared__ float cv[1024];
    __shared__ int   ct[1024];
    __shared__ float rv[256];
    __shared__ int   rt[256];
    __shared__ int   rs[256];
    __shared__ float red[256];
    __shared__ float c_lp[4][4];
    __shared__ int   c_v[4][4];

    for (int kk = 0; kk < 4; kk++) {
        int r = b * 4 + kk;
        // global max over partials
        float m = (tid < NBLK) ? g_pmax[r * NBLK + tid] : -3.4e38f;
        red[tid] = m;
        __syncthreads();
        for (int off = 128; off; off >>= 1) {
            if (tid < off) red[tid] = fmaxf(red[tid], red[tid + off]);
            __syncthreads();
        }
        float M = red[0];
        __syncthreads();
        // global sum
        float s = (tid < NBLK) ? g_psum[r * NBLK + tid] * expf(g_pmax[r * NBLK + tid] - M) : 0.f;
        red[tid] = s;
        __syncthreads();
        for (int off = 128; off; off >>= 1) {
            if (tid < off) red[tid] += red[tid + off];
            __syncthreads();
        }
        float lse = M + logf(red[0]);
        __syncthreads();
        // load 1000 candidates
        for (int i = tid; i < 1024; i += 256) {
            if (i < NBLK * 4) {
                cv[i] = g_ptv[(size_t)r * (NBLK * 4) + i];
                ct[i] = g_pti[(size_t)r * (NBLK * 4) + i];
            } else {
                cv[i] = -3.4e38f; ct[i] = 0x7fffffff;
            }
        }
        for (int round = 0; round < 4; round++) {
            __syncthreads();
            float bvv = -3.4e38f; int bt = 0x7fffffff; int bs = -1;
            for (int j = tid; j < 1024; j += 256) {
                float v = cv[j]; int tk = ct[j];
                if (v > bvv || (v == bvv && tk < bt)) { bvv = v; bt = tk; bs = j; }
            }
            rv[tid] = bvv; rt[tid] = bt; rs[tid] = bs;
            __syncthreads();
            for (int off = 128; off; off >>= 1) {
                if (tid < off) {
                    float v = rv[tid + off]; int tk = rt[tid + off];
                    if (v > rv[tid] || (v == rv[tid] && tk < rt[tid])) {
                        rv[tid] = v; rt[tid] = tk; rs[tid] = rs[tid + off];
                    }
                }
                __syncthreads();
            }
            if (tid == 0) {
                c_lp[kk][round] = rv[0] - lse;
                c_v[kk][round] = rt[0];
                cv[rs[0]] = -3.4e38f;
            }
        }
        __syncthreads();
    }

    if (t == 0) {
        // init: expand SOS beam (row kk=0) into top-K beams
        if (tid < 4) {
            int tok = c_v[0][tid];
            g_scores[0][b * 4 + tid] = c_lp[0][tid];
            g_fin[0][b * 4 + tid] = (tok == EOS_T) ? 1 : 0;
        }
        __syncthreads();
        for (int idx = tid; idx < 4 * TT; idx += 256) {
            int k = idx >> 6, p = idx & 63;
            int val = (p == 0) ? SOS_T : ((p == 1) ? c_v[0][k] : PAD_T);
            g_seqs[0][(b * 4 + k) * TT + p] = val;
        }
    } else {
        __shared__ float nsc[4];
        __shared__ int nbi[4], ntok[4], nfin[4];
        if (tid == 0) {
            float tot[16]; int tvv[16];
            for (int j = 0; j < 4; j++) {
                int f = g_fin[par][b * 4 + j];
                float sc = g_scores[par][b * 4 + j];
                for (int rr = 0; rr < 4; rr++) {
                    float lp; int v;
                    if (f) { lp = (rr == 0) ? 0.f : NEGV; v = PAD_T; }
                    else   { lp = c_lp[j][rr]; v = c_v[j][rr]; }
                    tot[j * 4 + rr] = sc + lp;
                    tvv[j * 4 + rr] = v;
                }
            }
            bool used[16];
            for (int i = 0; i < 16; i++) used[i] = false;
            for (int k = 0; k < 4; k++) {
                int best = -1;
                for (int i = 0; i < 16; i++)
                    if (!used[i] && (best < 0 || tot[i] > tot[best])) best = i;
                used[best] = true;
                nsc[k] = tot[best]; nbi[k] = best >> 2; ntok[k] = tvv[best];
            }
            for (int k = 0; k < 4; k++)
                nfin[k] = (g_fin[par][b * 4 + nbi[k]] || ntok[k] == EOS_T) ? 1 : 0;
        }
        __syncthreads();
        int np = par ^ 1;
        for (int idx = tid; idx < 4 * TT; idx += 256) {
            int k = idx >> 6, p = idx & 63;
            int src = g_seqs[par][(b * 4 + nbi[k]) * TT + p];
            g_seqs[np][(b * 4 + k) * TT + p] = (p == t) ? ntok[k] : src;
        }
        if (tid < 4) {
            g_scores[np][b * 4 + tid] = nsc[tid];
            g_fin[np][b * 4 + tid] = nfin[tid];
        }
    }
}

// ---------------- final selection + output ---------------------------------
__global__ void k_final(float* __restrict__ out, int out_size, int par)
{
    __shared__ int bk[16];
    __shared__ float bvv[16];
    int tid = threadIdx.x;   // 1024 threads
    if (tid < 16) {
        float bs = -3.4e38f; int bi = 0;
        for (int k = 0; k < 4; k++) {
            float v = g_scores[par][tid * 4 + k];
            if (v > bs) { bs = v; bi = k; }
        }
        bk[tid] = bi; bvv[tid] = bs;
    }
    __syncthreads();
    if (tid < BB * TT && tid < out_size) {
        int b = tid >> 6, p = tid & 63;
        out[tid] = (float)g_seqs[par][(b * 4 + bk[b]) * TT + p];
    }
    if (tid < 16 && BB * TT + tid < out_size)
        out[BB * TT + tid] = bvv[tid];
}

// ---------------- launch ----------------------------------------------------
extern "C" void kernel_launch(void* const* d_in, const int* in_sizes, int n_in,
                              void* d_out, int out_size)
{
    const float* enc  = (const float*)d_in[0];
    const int*   lens = (const int*)d_in[1];
    const float* emb  = (const float*)d_in[2];
    const float* Wq   = (const float*)d_in[3];
    const float* Wk   = (const float*)d_in[4];
    const float* Wfc  = (const float*)d_in[5];
    const float* bfc  = (const float*)d_in[6];
    float* out = (float*)d_out;
    float scale = 1.0f / sqrtf(512.0f);

    // encK = enc @ W_k
    k_gemm_encK<<<dim3(4, 128), 256>>>(enc, Wk);

    // step 1: expand SOS -> top-K beams
    k_embed_q<<<dim3(8, 16), 256>>>(emb, Wq, 1, 0, 0);
    k_attn<<<dim3(4, 16), 512>>>(lens, scale);
    k_ctx<<<dim3(8, 16), 256>>>(enc, emb, 1, 0, 0);
    k_gemm_logits<<<NBLK, 256>>>(Wfc, bfc);
    k_merge<<<16, 256>>>(0, 0);

    int par = 0;
    for (int t = 2; t < TT; t++) {
        k_embed_q<<<dim3(8, 16), 256>>>(emb, Wq, 0, t, par);
        k_attn<<<dim3(4, 16), 512>>>(lens, scale);
        k_ctx<<<dim3(8, 16), 256>>>(enc, emb, 0, t, par);
        k_gemm_logits<<<NBLK, 256>>>(Wfc, bfc);
        k_merge<<<16, 256>>>(t, par);
        par ^= 1;
    }

    k_final<<<1, 1024>>>(out, out_size, par);
}